// round 2
// baseline (speedup 1.0000x reference)
#include <cuda_runtime.h>
#include <cuda_bf16.h>

#define NN 100000
#define EE 1600000
#define IN_F 128
#define OUT_F 64
#define HH 8
#define DK 8

// Scratch (device globals; no allocation allowed)
__device__ float g_q[NN * OUT_F];
__device__ float g_k[NN * OUT_F];
__device__ float g_v[NN * OUT_F];
__device__ float g_denom[NN * HH];

// ---------------------------------------------------------------------------
// K1: fused QKV projection.  Block = 192 threads (one output column each:
// 0-63 -> Q, 64-127 -> K, 128-191 -> V).  32 node rows per block, x tile in
// smem as float4, broadcast LDS across the warp, W rows streamed from L1.
// ---------------------------------------------------------------------------
#define TILE_R 32

__global__ __launch_bounds__(192) void qkv_kernel(
    const float* __restrict__ x,
    const float* __restrict__ Wq, const float* __restrict__ bq,
    const float* __restrict__ Wk, const float* __restrict__ bk,
    const float* __restrict__ Wv, const float* __restrict__ bv)
{
    __shared__ float4 xs[TILE_R][IN_F / 4];  // 32 x 32 float4 = 16 KB

    const int c = threadIdx.x;           // 0..191
    const int row0 = blockIdx.x * TILE_R;

    // cooperative load of x tile (fully coalesced float4)
    const float4* x4 = reinterpret_cast<const float4*>(x);
    for (int i = c; i < TILE_R * (IN_F / 4); i += 192) {
        int r = i >> 5;          // /32
        int kk = i & 31;
        xs[r][kk] = x4[(size_t)(row0 + r) * (IN_F / 4) + kk];
    }
    __syncthreads();

    const float* Wrow;
    float bias;
    float* outp;
    int cc;
    if (c < 64)       { Wrow = Wq + c * IN_F;         bias = bq[c];       outp = g_q; cc = c; }
    else if (c < 128) { Wrow = Wk + (c - 64) * IN_F;  bias = bk[c - 64];  outp = g_k; cc = c - 64; }
    else              { Wrow = Wv + (c - 128) * IN_F; bias = bv[c - 128]; outp = g_v; cc = c - 128; }

    float acc[TILE_R];
#pragma unroll
    for (int r = 0; r < TILE_R; r++) acc[r] = 0.f;

    const float4* W4 = reinterpret_cast<const float4*>(Wrow);
#pragma unroll 4
    for (int kk = 0; kk < IN_F / 4; kk++) {
        float4 w = W4[kk];
#pragma unroll
        for (int r = 0; r < TILE_R; r++) {
            float4 xv = xs[r][kk];
            acc[r] += w.x * xv.x;
            acc[r] += w.y * xv.y;
            acc[r] += w.z * xv.z;
            acc[r] += w.w * xv.w;
        }
    }

#pragma unroll
    for (int r = 0; r < TILE_R; r++) {
        outp[(size_t)(row0 + r) * OUT_F + cc] = acc[r] + bias;
    }
}

// ---------------------------------------------------------------------------
// K2: fused edge pass.  8 threads per edge (one per head).  Each thread:
//   s   = <q[src,h,:], k[dst,h,:]> / sqrt(8)
//   ex  = exp(s)                     (no max-subtraction: scores are tiny,
//                                     result is mathematically identical)
//   denom[src,h] += ex               (scalar red)
//   out[src,h,:] += ex * v[dst,h,:]  (2x float4 vector red, sm_90+)
// edge is int32 [2, E] (JAX default x64-disabled downcasts int64 -> int32).
// ---------------------------------------------------------------------------
__global__ __launch_bounds__(256) void edge_kernel(
    const int* __restrict__ edge,   // [2, E] int32
    float* __restrict__ out)
{
    const long long t = (long long)blockIdx.x * blockDim.x + threadIdx.x;
    if (t >= (long long)EE * HH) return;
    const int e = (int)(t >> 3);
    const int h = (int)(t & 7);

    const int src = edge[e];
    const int dst = edge[EE + e];

    const float4* q4 = reinterpret_cast<const float4*>(g_q);
    const float4* k4 = reinterpret_cast<const float4*>(g_k);
    const float4* v4 = reinterpret_cast<const float4*>(g_v);

    const int qo = src * (OUT_F / 4) + h * 2;
    const int ko = dst * (OUT_F / 4) + h * 2;

    float4 qa = q4[qo],     qb = q4[qo + 1];
    float4 ka = k4[ko],     kb = k4[ko + 1];

    float s = qa.x * ka.x + qa.y * ka.y + qa.z * ka.z + qa.w * ka.w
            + qb.x * kb.x + qb.y * kb.y + qb.z * kb.z + qb.w * kb.w;
    s *= 0.35355339059327373f;  // 1/sqrt(8)

    float ex = __expf(s);

    atomicAdd(&g_denom[src * HH + h], ex);

    float4 va = v4[ko], vb = v4[ko + 1];
    float4 ma = make_float4(ex * va.x, ex * va.y, ex * va.z, ex * va.w);
    float4 mb = make_float4(ex * vb.x, ex * vb.y, ex * vb.z, ex * vb.w);

    float4* op = reinterpret_cast<float4*>(out) + src * (OUT_F / 4) + h * 2;
    atomicAdd(op, ma);       // RED.v4 on sm_90+
    atomicAdd(op + 1, mb);
}

// ---------------------------------------------------------------------------
// K3: normalize by segment denominator.
// ---------------------------------------------------------------------------
__global__ __launch_bounds__(256) void norm_kernel(float* __restrict__ out)
{
    int t = blockIdx.x * blockDim.x + threadIdx.x;
    if (t >= NN * OUT_F) return;
    out[t] = out[t] / (g_denom[t >> 3] + 1e-16f);
}

extern "C" void kernel_launch(void* const* d_in, const int* in_sizes, int n_in,
                              void* d_out, int out_size)
{
    const float* x    = (const float*)d_in[0];
    const int*   edge = (const int*)d_in[1];
    const float* Wq   = (const float*)d_in[2];
    const float* bq   = (const float*)d_in[3];
    const float* Wk   = (const float*)d_in[4];
    const float* bk   = (const float*)d_in[5];
    const float* Wv   = (const float*)d_in[6];
    const float* bv   = (const float*)d_in[7];
    float* out = (float*)d_out;

    void* dden = nullptr;
    cudaGetSymbolAddress(&dden, g_denom);
    cudaMemsetAsync(dden, 0, (size_t)NN * HH * sizeof(float));
    cudaMemsetAsync(out, 0, (size_t)out_size * sizeof(float));

    // K1: QKV.  100000 / 32 = 3125 blocks exactly.
    qkv_kernel<<<NN / TILE_R, 192>>>(x, Wq, bq, Wk, bk, Wv, bv);

    // K2: fused edge pass. E*8 = 12.8M threads.
    {
        long long total = (long long)EE * HH;
        int blocks = (int)((total + 255) / 256);
        edge_kernel<<<blocks, 256>>>(edge, out);
    }

    // K3: normalize.
    norm_kernel<<<(NN * OUT_F + 255) / 256, 256>>>(out);
}

// round 3
// speedup vs baseline: 1.4576x; 1.4576x over previous
#include <cuda_runtime.h>
#include <cuda_fp16.h>

#define NN 100000
#define EE 1600000
#define IN_F 128
#define OUT_F 64
#define HH 8

// Scratch (device globals; no allocation allowed).
// q/k/v stored as fp16 to halve the L2 gather traffic in the edge pass.
__device__ __half g_qh[NN * OUT_F];
__device__ __half g_kh[NN * OUT_F];
__device__ __half g_vh[NN * OUT_F];
__device__ float  g_denom[NN * HH];

// ---------------------------------------------------------------------------
// K1: register-tiled QKV GEMM.  C[N,64] = x[N,128] @ W^T + b, one of Q/K/V
// selected by blockIdx.y.  BM=64 rows, BN=64 cols (full matrix), BK=32.
// 128 threads, each computes a 4x8 tile => 3 LDS.128 per 32 FFMA.
// ---------------------------------------------------------------------------
#define BM 64
#define BN 64
#define BK 32
#define XS_LD (BM + 4)   // padded row stride (words); multiple of 4 so float4 reads stay aligned
#define WS_LD (BN + 4)

__global__ __launch_bounds__(128) void qkv_gemm(
    const float* __restrict__ x,
    const float* __restrict__ Wq, const float* __restrict__ bq,
    const float* __restrict__ Wk, const float* __restrict__ bk,
    const float* __restrict__ Wv, const float* __restrict__ bv)
{
    __shared__ float xs[BK][XS_LD];
    __shared__ float ws[BK][WS_LD];

    const float* W;  const float* bias;  __half* outp;
    if (blockIdx.y == 0)      { W = Wq; bias = bq; outp = g_qh; }
    else if (blockIdx.y == 1) { W = Wk; bias = bk; outp = g_kh; }
    else                      { W = Wv; bias = bv; outp = g_vh; }

    const int tid  = threadIdx.x;            // 0..127
    const int row0 = blockIdx.x * BM;
    const int tm   = (tid & 15) * 4;          // thread row offset   0..60
    const int tn   = (tid >> 4) * 8;          // thread col offset   0..56

    float acc[4][8];
#pragma unroll
    for (int i = 0; i < 4; i++)
#pragma unroll
        for (int j = 0; j < 8; j++) acc[i][j] = 0.f;

    const float4* x4 = reinterpret_cast<const float4*>(x);
    const float4* W4 = reinterpret_cast<const float4*>(W);

    for (int k0 = 0; k0 < IN_F; k0 += BK) {
        // ---- load x tile (64 rows x 32 k), transposed into xs[k][m] ----
#pragma unroll
        for (int jj = 0; jj < 4; jj++) {
            int idx = tid + 128 * jj;          // 0..511
            int r   = idx >> 3;                // 0..63
            int f4  = idx & 7;                 // 0..7  (float4 within k-span)
            int row = row0 + r;
            if (row >= NN) row = NN - 1;       // clamp; invalid rows never stored
            float4 v = x4[(size_t)row * (IN_F / 4) + (k0 >> 2) + f4];
            int kk = f4 * 4;
            xs[kk + 0][r] = v.x;
            xs[kk + 1][r] = v.y;
            xs[kk + 2][r] = v.z;
            xs[kk + 3][r] = v.w;
        }
        // ---- load W tile (64 cols x 32 k), transposed into ws[k][c] ----
#pragma unroll
        for (int jj = 0; jj < 4; jj++) {
            int idx = tid + 128 * jj;
            int c   = idx >> 3;
            int f4  = idx & 7;
            float4 v = W4[(size_t)c * (IN_F / 4) + (k0 >> 2) + f4];
            int kk = f4 * 4;
            ws[kk + 0][c] = v.x;
            ws[kk + 1][c] = v.y;
            ws[kk + 2][c] = v.z;
            ws[kk + 3][c] = v.w;
        }
        __syncthreads();

#pragma unroll
        for (int kk = 0; kk < BK; kk++) {
            float4 a  = *reinterpret_cast<const float4*>(&xs[kk][tm]);
            float4 b0 = *reinterpret_cast<const float4*>(&ws[kk][tn]);
            float4 b1 = *reinterpret_cast<const float4*>(&ws[kk][tn + 4]);
            float av[4] = {a.x, a.y, a.z, a.w};
            float bv8[8] = {b0.x, b0.y, b0.z, b0.w, b1.x, b1.y, b1.z, b1.w};
#pragma unroll
            for (int i = 0; i < 4; i++)
#pragma unroll
                for (int j = 0; j < 8; j++)
                    acc[i][j] += av[i] * bv8[j];
        }
        __syncthreads();
    }

    // ---- epilogue: add bias, convert to fp16, 16B stores ----
    float bj[8];
#pragma unroll
    for (int j = 0; j < 8; j++) bj[j] = bias[tn + j];

#pragma unroll
    for (int i = 0; i < 4; i++) {
        int row = row0 + tm + i;
        if (row < NN) {
            __half h[8];
#pragma unroll
            for (int j = 0; j < 8; j++) h[j] = __float2half_rn(acc[i][j] + bj[j]);
            *reinterpret_cast<uint4*>(&outp[(size_t)row * OUT_F + tn]) =
                *reinterpret_cast<const uint4*>(h);
        }
    }
}

// ---------------------------------------------------------------------------
// K2: fused edge pass, fp16 gathers.  8 threads per edge (one per head).
//   s  = <q[src,h,:], k[dst,h,:]> / sqrt(8)      (fp32 accumulate)
//   ex = exp(s)   (scores tiny; skipping max-subtraction is exact in math)
//   denom[src,h] += ex ;  out[src,h,:] += ex * v[dst,h,:]  (RED.v4)
// ---------------------------------------------------------------------------
__global__ __launch_bounds__(256) void edge_kernel(
    const int* __restrict__ edge,   // [2, E] int32
    float* __restrict__ out)
{
    const long long t = (long long)blockIdx.x * blockDim.x + threadIdx.x;
    if (t >= (long long)EE * HH) return;
    const int e = (int)(t >> 3);
    const int h = (int)(t & 7);

    const int src = edge[e];
    const int dst = edge[EE + e];

    const uint4* qh = reinterpret_cast<const uint4*>(g_qh);  // 8 halves per (node,head)
    const uint4* kh = reinterpret_cast<const uint4*>(g_kh);
    const uint4* vh = reinterpret_cast<const uint4*>(g_vh);

    uint4 qv = qh[src * HH + h];
    uint4 kv = kh[dst * HH + h];

    const __half2* q2 = reinterpret_cast<const __half2*>(&qv);
    const __half2* k2 = reinterpret_cast<const __half2*>(&kv);

    float s = 0.f;
#pragma unroll
    for (int i = 0; i < 4; i++) {
        float2 a = __half22float2(q2[i]);
        float2 b = __half22float2(k2[i]);
        s += a.x * b.x + a.y * b.y;
    }
    s *= 0.35355339059327373f;  // 1/sqrt(8)
    float ex = __expf(s);

    atomicAdd(&g_denom[src * HH + h], ex);

    uint4 vv = vh[dst * HH + h];
    const __half2* v2 = reinterpret_cast<const __half2*>(&vv);
    float2 v01 = __half22float2(v2[0]);
    float2 v23 = __half22float2(v2[1]);
    float2 v45 = __half22float2(v2[2]);
    float2 v67 = __half22float2(v2[3]);

    float4 ma = make_float4(ex * v01.x, ex * v01.y, ex * v23.x, ex * v23.y);
    float4 mb = make_float4(ex * v45.x, ex * v45.y, ex * v67.x, ex * v67.y);

    float4* op = reinterpret_cast<float4*>(out) + src * (OUT_F / 4) + h * 2;
    atomicAdd(op, ma);       // RED.v4 on sm_90+
    atomicAdd(op + 1, mb);
}

// ---------------------------------------------------------------------------
// K3: normalize by segment denominator.
// ---------------------------------------------------------------------------
__global__ __launch_bounds__(256) void norm_kernel(float* __restrict__ out)
{
    int t = blockIdx.x * blockDim.x + threadIdx.x;
    if (t >= NN * OUT_F) return;
    out[t] = out[t] / (g_denom[t >> 3] + 1e-16f);
}

extern "C" void kernel_launch(void* const* d_in, const int* in_sizes, int n_in,
                              void* d_out, int out_size)
{
    const float* x    = (const float*)d_in[0];
    const int*   edge = (const int*)d_in[1];
    const float* Wq   = (const float*)d_in[2];
    const float* bq   = (const float*)d_in[3];
    const float* Wk   = (const float*)d_in[4];
    const float* bk   = (const float*)d_in[5];
    const float* Wv   = (const float*)d_in[6];
    const float* bv   = (const float*)d_in[7];
    float* out = (float*)d_out;

    void* dden = nullptr;
    cudaGetSymbolAddress(&dden, g_denom);
    cudaMemsetAsync(dden, 0, (size_t)NN * HH * sizeof(float));
    cudaMemsetAsync(out, 0, (size_t)out_size * sizeof(float));

    // K1: QKV GEMM.  grid = (ceil(N/64), 3 matrices)
    dim3 g1((NN + BM - 1) / BM, 3);
    qkv_gemm<<<g1, 128>>>(x, Wq, bq, Wk, bk, Wv, bv);

    // K2: fused edge pass. E*8 = 12.8M threads.
    {
        long long total = (long long)EE * HH;
        int blocks = (int)((total + 255) / 256);
        edge_kernel<<<blocks, 256>>>(edge, out);
    }

    // K3: normalize.
    norm_kernel<<<(NN * OUT_F + 255) / 256, 256>>>(out);
}

// round 4
// speedup vs baseline: 1.8430x; 1.2644x over previous
#include <cuda_runtime.h>
#include <cuda_fp16.h>

#define NN 100000
#define EE 1600000
#define IN_F 128
#define OUT_F 64
#define HH 8

// ---------------------------------------------------------------------------
// Device-global scratch (no allocations allowed)
// ---------------------------------------------------------------------------
__device__ __half g_qh[NN * OUT_F];
__device__ __half g_kh[NN * OUT_F];
__device__ __half g_vh[NN * OUT_F];

__device__ int g_deg[NN];        // per-src edge count
__device__ int g_off[NN + 1];    // CSR row offsets
__device__ int g_cur[NN];        // scatter cursors
__device__ int g_csr_dst[EE];    // dst node per edge, grouped by src
__device__ int g_bsums[128];     // block sums for 2-level scan

// packed fp32x2 helpers (Blackwell dual-FMA; ptxas never auto-generates)
#define PACK2(out, lo, hi) \
    asm("mov.b64 %0, {%1, %2};" : "=l"(out) : "f"(lo), "f"(hi))
#define FMA2(d, a, b, c) \
    asm("fma.rn.f32x2 %0, %1, %2, %3;" : "=l"(d) : "l"(a), "l"(b), "l"(c))
#define UNPACK2(lo, hi, in) \
    asm("mov.b64 {%0, %1}, %2;" : "=f"(lo), "=f"(hi) : "l"(in))

// ---------------------------------------------------------------------------
// K1: register-tiled QKV GEMM with packed f32x2 FMA.
// C[N,64] = x[N,128] @ W^T + b; blockIdx.y selects Q/K/V. BM=64,BN=64,BK=32,
// 128 threads, each computes 4 rows x 8 cols (as 4x4 packed pairs).
// ---------------------------------------------------------------------------
#define BM 64
#define BN 64
#define BK 32
#define XS_LD (BM + 4)
#define WS_LD (BN + 4)

__global__ __launch_bounds__(128) void qkv_gemm(
    const float* __restrict__ x,
    const float* __restrict__ Wq, const float* __restrict__ bq,
    const float* __restrict__ Wk, const float* __restrict__ bk,
    const float* __restrict__ Wv, const float* __restrict__ bv)
{
    __shared__ float xs[BK][XS_LD];
    __shared__ float ws[BK][WS_LD];

    const float* W;  const float* bias;  __half* outp;
    if (blockIdx.y == 0)      { W = Wq; bias = bq; outp = g_qh; }
    else if (blockIdx.y == 1) { W = Wk; bias = bk; outp = g_kh; }
    else                      { W = Wv; bias = bv; outp = g_vh; }

    const int tid  = threadIdx.x;
    const int row0 = blockIdx.x * BM;
    const int tm   = (tid & 15) * 4;
    const int tn   = (tid >> 4) * 8;

    unsigned long long acc[4][4];
#pragma unroll
    for (int i = 0; i < 4; i++)
#pragma unroll
        for (int p = 0; p < 4; p++) acc[i][p] = 0ull;

    const float4* x4 = reinterpret_cast<const float4*>(x);
    const float4* W4 = reinterpret_cast<const float4*>(W);

    for (int k0 = 0; k0 < IN_F; k0 += BK) {
#pragma unroll
        for (int jj = 0; jj < 4; jj++) {
            int idx = tid + 128 * jj;
            int r   = idx >> 3;
            int f4  = idx & 7;
            int row = row0 + r;
            if (row >= NN) row = NN - 1;
            float4 v = x4[(size_t)row * (IN_F / 4) + (k0 >> 2) + f4];
            int kk = f4 * 4;
            xs[kk + 0][r] = v.x;  xs[kk + 1][r] = v.y;
            xs[kk + 2][r] = v.z;  xs[kk + 3][r] = v.w;
        }
#pragma unroll
        for (int jj = 0; jj < 4; jj++) {
            int idx = tid + 128 * jj;
            int c   = idx >> 3;
            int f4  = idx & 7;
            float4 v = W4[(size_t)c * (IN_F / 4) + (k0 >> 2) + f4];
            int kk = f4 * 4;
            ws[kk + 0][c] = v.x;  ws[kk + 1][c] = v.y;
            ws[kk + 2][c] = v.z;  ws[kk + 3][c] = v.w;
        }
        __syncthreads();

#pragma unroll
        for (int kk = 0; kk < BK; kk++) {
            float4 a  = *reinterpret_cast<const float4*>(&xs[kk][tm]);
            float4 b0 = *reinterpret_cast<const float4*>(&ws[kk][tn]);
            float4 b1 = *reinterpret_cast<const float4*>(&ws[kk][tn + 4]);
            unsigned long long bp[4];
            PACK2(bp[0], b0.x, b0.y);  PACK2(bp[1], b0.z, b0.w);
            PACK2(bp[2], b1.x, b1.y);  PACK2(bp[3], b1.z, b1.w);
            float av[4] = {a.x, a.y, a.z, a.w};
#pragma unroll
            for (int i = 0; i < 4; i++) {
                unsigned long long aa;
                PACK2(aa, av[i], av[i]);
#pragma unroll
                for (int p = 0; p < 4; p++)
                    FMA2(acc[i][p], aa, bp[p], acc[i][p]);
            }
        }
        __syncthreads();
    }

    float bj[8];
#pragma unroll
    for (int j = 0; j < 8; j++) bj[j] = bias[tn + j];

#pragma unroll
    for (int i = 0; i < 4; i++) {
        int row = row0 + tm + i;
        if (row < NN) {
            float f[8];
#pragma unroll
            for (int p = 0; p < 4; p++)
                UNPACK2(f[2 * p], f[2 * p + 1], acc[i][p]);
            __half h[8];
#pragma unroll
            for (int j = 0; j < 8; j++) h[j] = __float2half_rn(f[j] + bj[j]);
            *reinterpret_cast<uint4*>(&outp[(size_t)row * OUT_F + tn]) =
                *reinterpret_cast<const uint4*>(h);
        }
    }
}

// ---------------------------------------------------------------------------
// CSR build: count -> 2-level exclusive scan -> scatter
// ---------------------------------------------------------------------------
__global__ __launch_bounds__(256) void count_kernel(const int* __restrict__ edge)
{
    int e = blockIdx.x * blockDim.x + threadIdx.x;
    if (e < EE) atomicAdd(&g_deg[edge[e]], 1);
}

#define SCAN_B 1024
#define SCAN_NB ((NN + SCAN_B - 1) / SCAN_B)   // 98

__global__ __launch_bounds__(SCAN_B) void scan1_kernel()
{
    __shared__ int sh[SCAN_B];
    int t = threadIdx.x;
    int i = blockIdx.x * SCAN_B + t;
    sh[t] = (i < NN) ? g_deg[i] : 0;
    __syncthreads();
    // block reduce
    for (int ofs = SCAN_B / 2; ofs > 0; ofs >>= 1) {
        if (t < ofs) sh[t] += sh[t + ofs];
        __syncthreads();
    }
    if (t == 0) g_bsums[blockIdx.x] = sh[0];
}

__global__ void scan2_kernel()
{
    // single thread: exclusive scan of SCAN_NB block sums
    if (threadIdx.x == 0) {
        int run = 0;
        for (int b = 0; b < SCAN_NB; b++) {
            int v = g_bsums[b];
            g_bsums[b] = run;
            run += v;
        }
        g_off[NN] = run;   // == EE
    }
}

__global__ __launch_bounds__(SCAN_B) void scan3_kernel()
{
    __shared__ int sh[SCAN_B];
    int t = threadIdx.x;
    int i = blockIdx.x * SCAN_B + t;
    int val = (i < NN) ? g_deg[i] : 0;
    sh[t] = val;
    __syncthreads();
    // Hillis-Steele inclusive scan
    for (int ofs = 1; ofs < SCAN_B; ofs <<= 1) {
        int xv = (t >= ofs) ? sh[t - ofs] : 0;
        __syncthreads();
        sh[t] += xv;
        __syncthreads();
    }
    if (i < NN) {
        int excl = sh[t] - val + g_bsums[blockIdx.x];
        g_off[i] = excl;
        g_cur[i] = excl;
    }
}

__global__ __launch_bounds__(256) void scatter_kernel(const int* __restrict__ edge)
{
    int e = blockIdx.x * blockDim.x + threadIdx.x;
    if (e < EE) {
        int s = edge[e];
        int d = edge[EE + e];
        int pos = atomicAdd(&g_cur[s], 1);
        g_csr_dst[pos] = d;
    }
}

// ---------------------------------------------------------------------------
// K2: warp-per-node aggregation.  lane = (j, h): j = edge slot (4 at a time),
// h = head.  Softmax denominator + weighted sum accumulated in registers,
// cross-lane reduced with shuffles, normalized, stored once.  No atomics.
// ---------------------------------------------------------------------------
__global__ __launch_bounds__(256) void agg_kernel(float* __restrict__ out)
{
    const int node = blockIdx.x * 8 + (threadIdx.x >> 5);
    if (node >= NN) return;
    const int lane = threadIdx.x & 31;
    const int h = lane & 7;
    const int j = lane >> 3;

    // q row for this head (same for the 4 j-lanes of this h)
    uint4 qv = *reinterpret_cast<const uint4*>(&g_qh[node * OUT_F + h * 8]);
    const __half2* q2 = reinterpret_cast<const __half2*>(&qv);
    float qf[8];
#pragma unroll
    for (int i = 0; i < 4; i++) {
        float2 f = __half22float2(q2[i]);
        qf[2 * i] = f.x;  qf[2 * i + 1] = f.y;
    }

    const int beg = g_off[node];
    const int end = g_off[node + 1];

    float den = 0.f;
    float acc[8];
#pragma unroll
    for (int d = 0; d < 8; d++) acc[d] = 0.f;

    for (int e = beg + j; e < end; e += 4) {
        int dst = g_csr_dst[e];
        uint4 kv = *reinterpret_cast<const uint4*>(&g_kh[dst * OUT_F + h * 8]);
        const __half2* k2 = reinterpret_cast<const __half2*>(&kv);
        float s = 0.f;
#pragma unroll
        for (int i = 0; i < 4; i++) {
            float2 f = __half22float2(k2[i]);
            s += qf[2 * i] * f.x + qf[2 * i + 1] * f.y;
        }
        float ex = __expf(s * 0.35355339059327373f);
        den += ex;

        uint4 vv = *reinterpret_cast<const uint4*>(&g_vh[dst * OUT_F + h * 8]);
        const __half2* v2 = reinterpret_cast<const __half2*>(&vv);
#pragma unroll
        for (int i = 0; i < 4; i++) {
            float2 f = __half22float2(v2[i]);
            acc[2 * i]     += ex * f.x;
            acc[2 * i + 1] += ex * f.y;
        }
    }

    // combine the 4 j-lanes of each head (lanes h, h+8, h+16, h+24)
#pragma unroll
    for (int m = 8; m <= 16; m <<= 1) {
        den += __shfl_xor_sync(0xffffffffu, den, m);
#pragma unroll
        for (int d = 0; d < 8; d++)
            acc[d] += __shfl_xor_sync(0xffffffffu, acc[d], m);
    }

    if (j == 0) {
        float inv = 1.f / (den + 1e-16f);
        float4 o0 = make_float4(acc[0] * inv, acc[1] * inv, acc[2] * inv, acc[3] * inv);
        float4 o1 = make_float4(acc[4] * inv, acc[5] * inv, acc[6] * inv, acc[7] * inv);
        float4* op = reinterpret_cast<float4*>(&out[node * OUT_F + h * 8]);
        op[0] = o0;
        op[1] = o1;
    }
}

extern "C" void kernel_launch(void* const* d_in, const int* in_sizes, int n_in,
                              void* d_out, int out_size)
{
    const float* x    = (const float*)d_in[0];
    const int*   edge = (const int*)d_in[1];
    const float* Wq   = (const float*)d_in[2];
    const float* bq   = (const float*)d_in[3];
    const float* Wk   = (const float*)d_in[4];
    const float* bk   = (const float*)d_in[5];
    const float* Wv   = (const float*)d_in[6];
    const float* bv   = (const float*)d_in[7];
    float* out = (float*)d_out;

    void* ddeg = nullptr;
    cudaGetSymbolAddress(&ddeg, g_deg);
    cudaMemsetAsync(ddeg, 0, (size_t)NN * sizeof(int));

    // K1: QKV GEMM
    dim3 g1((NN + BM - 1) / BM, 3);
    qkv_gemm<<<g1, 128>>>(x, Wq, bq, Wk, bk, Wv, bv);

    // CSR build
    count_kernel<<<(EE + 255) / 256, 256>>>(edge);
    scan1_kernel<<<SCAN_NB, SCAN_B>>>();
    scan2_kernel<<<1, 32>>>();
    scan3_kernel<<<SCAN_NB, SCAN_B>>>();
    scatter_kernel<<<(EE + 255) / 256, 256>>>(edge);

    // K2: aggregate (fused softmax + spmm + normalize)
    agg_kernel<<<(NN + 7) / 8, 256>>>(out);
}

// round 5
// speedup vs baseline: 2.5134x; 1.3638x over previous
#include <cuda_runtime.h>
#include <cuda_fp16.h>

#define NN 100000
#define EE 1600000
#define IN_F 128
#define OUT_F 64
#define HH 8

// ---------------------------------------------------------------------------
// Device-global scratch (no allocations allowed)
// ---------------------------------------------------------------------------
__device__ __half g_qh[NN * OUT_F];
__device__ __half g_kh[NN * OUT_F];
__device__ __half g_vh[NN * OUT_F];

__device__ uint2 g_wf[192 * 8 * 4];   // W fp16, HMMA-B fragment order
__device__ float g_bias[192];          // bq|bk|bv concatenated

__device__ int g_deg[NN];
__device__ int g_off[NN + 1];
__device__ int g_cur[NN];
__device__ int g_csr_dst[EE];
__device__ int g_bsums[128];

// ---------------------------------------------------------------------------
// K0: init — zero degree counters, pack W into fragment order, pack biases.
// Fragment layout: for (n, kb, j): halves {W[n][16kb+2j], W[n][16kb+2j+1],
//                                          W[n][16kb+2j+8], W[n][16kb+2j+9]}
// so lane l (j=l&3, n_local=l>>2) gets b0,b1 of mma.m16n8k16 in ONE LDG.64.
// ---------------------------------------------------------------------------
__global__ __launch_bounds__(256) void init_kernel(
    const float* __restrict__ Wq, const float* __restrict__ bq,
    const float* __restrict__ Wk, const float* __restrict__ bk,
    const float* __restrict__ Wv, const float* __restrict__ bv)
{
    int idx = blockIdx.x * blockDim.x + threadIdx.x;
    if (idx < NN) g_deg[idx] = 0;

    if (idx < 192 * 8 * 4) {
        int j  = idx & 3;
        int kb = (idx >> 2) & 7;
        int n  = idx >> 5;
        const float* Wr = (n < 64) ? (Wq + n * IN_F)
                        : (n < 128) ? (Wk + (n - 64) * IN_F)
                                    : (Wv + (n - 128) * IN_F);
        int k = kb * 16 + 2 * j;
        __half2 lo = __floats2half2_rn(Wr[k],     Wr[k + 1]);
        __half2 hi = __floats2half2_rn(Wr[k + 8], Wr[k + 9]);
        uint2 pk;
        pk.x = *reinterpret_cast<unsigned*>(&lo);
        pk.y = *reinterpret_cast<unsigned*>(&hi);
        g_wf[idx] = pk;
    }
    if (idx < 192) {
        g_bias[idx] = (idx < 64) ? bq[idx] : (idx < 128) ? bk[idx - 64] : bv[idx - 128];
    }
}

// ---------------------------------------------------------------------------
// K1: QKV GEMM on tensor cores.  Block: 256 threads (8 warps), 64 rows,
// all 192 output cols (Q|K|V).  A tile fp16 in smem (ldmatrix.x4), B from
// fragment-packed global (L1-resident, one LDG.64 per n-tile per k-step).
// ---------------------------------------------------------------------------
#define XS_LDH 136   // half stride: 272B (16B aligned for ldmatrix, conflict-free)

__global__ __launch_bounds__(256) void qkv_gemm(const float* __restrict__ x)
{
    __shared__ __half Xs[64][XS_LDH];

    const int tid = threadIdx.x;
    const int w = tid >> 5, l = tid & 31;
    const int row0 = blockIdx.x * 64;

    // ---- load + convert x tile: 64 x 128 fp32 -> fp16 smem ----
    const float4* x4 = reinterpret_cast<const float4*>(x);
#pragma unroll
    for (int i = 0; i < 8; i++) {
        int idx = tid + 256 * i;       // 0..2047
        int r = idx >> 5, c4 = idx & 31;
        int row = row0 + r;
        if (row >= NN) row = NN - 1;
        float4 v = x4[(size_t)row * 32 + c4];
        __half2 h0 = __floats2half2_rn(v.x, v.y);
        __half2 h1 = __floats2half2_rn(v.z, v.w);
        uint2 pk;
        pk.x = *reinterpret_cast<unsigned*>(&h0);
        pk.y = *reinterpret_cast<unsigned*>(&h1);
        *reinterpret_cast<uint2*>(&Xs[r][c4 * 4]) = pk;
    }
    __syncthreads();

    const int wm = w & 3;            // m-slice: rows wm*16 .. +15
    const int nh = w >> 2;           // n-half: 0 -> cols 0..95, 1 -> 96..191
    const int m0 = wm * 16;
    const int g = l >> 2, j = l & 3;

    float c[12][4];
#pragma unroll
    for (int t = 0; t < 12; t++)
#pragma unroll
        for (int p = 0; p < 4; p++) c[t][p] = 0.f;

    // ldmatrix lane address (4x 8x8 matrices: rows0-7/8-15 x klo/khi)
    const int sel = l >> 3;
    const int a_row = m0 + ((sel & 1) << 3) + (l & 7);
    const int a_col = (sel >> 1) << 3;

#pragma unroll
    for (int kb = 0; kb < 8; kb++) {
        unsigned a0, a1, a2, a3;
        unsigned sa = (unsigned)__cvta_generic_to_shared(&Xs[a_row][kb * 16 + a_col]);
        asm volatile("ldmatrix.sync.aligned.m8n8.x4.shared.b16 {%0,%1,%2,%3}, [%4];"
                     : "=r"(a0), "=r"(a1), "=r"(a2), "=r"(a3) : "r"(sa));

        uint2 bfr[12];
#pragma unroll
        for (int t = 0; t < 12; t++) {
            int n = nh * 96 + t * 8 + g;
            bfr[t] = g_wf[(n * 8 + kb) * 4 + j];
        }
#pragma unroll
        for (int t = 0; t < 12; t++) {
            asm volatile(
                "mma.sync.aligned.m16n8k16.row.col.f32.f16.f16.f32 "
                "{%0,%1,%2,%3}, {%4,%5,%6,%7}, {%8,%9}, {%0,%1,%2,%3};"
                : "+f"(c[t][0]), "+f"(c[t][1]), "+f"(c[t][2]), "+f"(c[t][3])
                : "r"(a0), "r"(a1), "r"(a2), "r"(a3), "r"(bfr[t].x), "r"(bfr[t].y));
        }
    }

    // ---- epilogue: bias, fp16, store to g_qh/g_kh/g_vh ----
    const int r0g = row0 + m0 + g;
    const int r1g = r0g + 8;
#pragma unroll
    for (int t = 0; t < 12; t++) {
        int n = nh * 96 + t * 8 + 2 * j;       // even
        float2 bb = *reinterpret_cast<const float2*>(&g_bias[n]);
        int m = n >> 6, col = n & 63;
        __half* base = (m == 0) ? g_qh : (m == 1) ? g_kh : g_vh;
        __half2 h0 = __floats2half2_rn(c[t][0] + bb.x, c[t][1] + bb.y);
        __half2 h1 = __floats2half2_rn(c[t][2] + bb.x, c[t][3] + bb.y);
        if (r0g < NN) *reinterpret_cast<__half2*>(&base[(size_t)r0g * 64 + col]) = h0;
        if (r1g < NN) *reinterpret_cast<__half2*>(&base[(size_t)r1g * 64 + col]) = h1;
    }
}

// ---------------------------------------------------------------------------
// CSR build: count -> block sums -> scan (prefix recomputed per block) -> scatter
// ---------------------------------------------------------------------------
__global__ __launch_bounds__(256) void count_kernel(const int* __restrict__ edge)
{
    int e = blockIdx.x * blockDim.x + threadIdx.x;
    if (e < EE) atomicAdd(&g_deg[edge[e]], 1);
}

#define SCAN_B 1024
#define SCAN_NB ((NN + SCAN_B - 1) / SCAN_B)   // 98

__global__ __launch_bounds__(SCAN_B) void scan1_kernel()
{
    __shared__ int sh[SCAN_B];
    int t = threadIdx.x;
    int i = blockIdx.x * SCAN_B + t;
    sh[t] = (i < NN) ? g_deg[i] : 0;
    __syncthreads();
    for (int ofs = SCAN_B / 2; ofs > 0; ofs >>= 1) {
        if (t < ofs) sh[t] += sh[t + ofs];
        __syncthreads();
    }
    if (t == 0) g_bsums[blockIdx.x] = sh[0];
}

__global__ __launch_bounds__(SCAN_B) void scan3_kernel()
{
    __shared__ int sh[SCAN_B];
    __shared__ int pre;
    int t = threadIdx.x;
    if (t == 0) pre = 0;
    __syncthreads();
    // prefix of preceding block sums (blockIdx.x <= 97 < 128)
    if (t < 128) {
        int pv = (t < blockIdx.x) ? g_bsums[t] : 0;
#pragma unroll
        for (int m = 16; m; m >>= 1) pv += __shfl_xor_sync(0xffffffffu, pv, m);
        if ((t & 31) == 0) atomicAdd(&pre, pv);
    }
    int i = blockIdx.x * SCAN_B + t;
    int val = (i < NN) ? g_deg[i] : 0;
    sh[t] = val;
    __syncthreads();
    for (int ofs = 1; ofs < SCAN_B; ofs <<= 1) {
        int xv = (t >= ofs) ? sh[t - ofs] : 0;
        __syncthreads();
        sh[t] += xv;
        __syncthreads();
    }
    if (i < NN) {
        int excl = sh[t] - val + pre;
        g_off[i] = excl;
        g_cur[i] = excl;
        if (i == NN - 1) g_off[NN] = sh[t] + pre;   // == EE
    }
}

__global__ __launch_bounds__(256) void scatter_kernel(const int* __restrict__ edge)
{
    int e = blockIdx.x * blockDim.x + threadIdx.x;
    if (e < EE) {
        int s = edge[e];
        int d = edge[EE + e];
        int pos = atomicAdd(&g_cur[s], 1);
        g_csr_dst[pos] = d;
    }
}

// ---------------------------------------------------------------------------
// K2: warp-per-node aggregation.  lane = (j,h); fused softmax+spmm+normalize.
// ---------------------------------------------------------------------------
__global__ __launch_bounds__(256) void agg_kernel(float* __restrict__ out)
{
    const int node = blockIdx.x * 8 + (threadIdx.x >> 5);
    if (node >= NN) return;
    const int lane = threadIdx.x & 31;
    const int h = lane & 7;
    const int j = lane >> 3;

    uint4 qv = *reinterpret_cast<const uint4*>(&g_qh[node * OUT_F + h * 8]);
    const __half2* q2 = reinterpret_cast<const __half2*>(&qv);
    float qf[8];
#pragma unroll
    for (int i = 0; i < 4; i++) {
        float2 f = __half22float2(q2[i]);
        qf[2 * i] = f.x;  qf[2 * i + 1] = f.y;
    }

    const int beg = g_off[node];
    const int end = g_off[node + 1];

    float den = 0.f;
    float acc[8];
#pragma unroll
    for (int d = 0; d < 8; d++) acc[d] = 0.f;

    for (int e = beg + j; e < end; e += 4) {
        int dst = g_csr_dst[e];
        // issue both gathers up front (independent addresses)
        uint4 kv = *reinterpret_cast<const uint4*>(&g_kh[dst * OUT_F + h * 8]);
        uint4 vv = *reinterpret_cast<const uint4*>(&g_vh[dst * OUT_F + h * 8]);
        const __half2* k2 = reinterpret_cast<const __half2*>(&kv);
        float s = 0.f;
#pragma unroll
        for (int i = 0; i < 4; i++) {
            float2 f = __half22float2(k2[i]);
            s += qf[2 * i] * f.x + qf[2 * i + 1] * f.y;
        }
        float ex = __expf(s * 0.35355339059327373f);
        den += ex;

        const __half2* v2 = reinterpret_cast<const __half2*>(&vv);
#pragma unroll
        for (int i = 0; i < 4; i++) {
            float2 f = __half22float2(v2[i]);
            acc[2 * i]     += ex * f.x;
            acc[2 * i + 1] += ex * f.y;
        }
    }

#pragma unroll
    for (int m = 8; m <= 16; m <<= 1) {
        den += __shfl_xor_sync(0xffffffffu, den, m);
#pragma unroll
        for (int d = 0; d < 8; d++)
            acc[d] += __shfl_xor_sync(0xffffffffu, acc[d], m);
    }

    if (j == 0) {
        float inv = 1.f / (den + 1e-16f);
        float4 o0 = make_float4(acc[0] * inv, acc[1] * inv, acc[2] * inv, acc[3] * inv);
        float4 o1 = make_float4(acc[4] * inv, acc[5] * inv, acc[6] * inv, acc[7] * inv);
        float4* op = reinterpret_cast<float4*>(&out[node * OUT_F + h * 8]);
        op[0] = o0;
        op[1] = o1;
    }
}

extern "C" void kernel_launch(void* const* d_in, const int* in_sizes, int n_in,
                              void* d_out, int out_size)
{
    const float* x    = (const float*)d_in[0];
    const int*   edge = (const int*)d_in[1];
    const float* Wq   = (const float*)d_in[2];
    const float* bq   = (const float*)d_in[3];
    const float* Wk   = (const float*)d_in[4];
    const float* bk   = (const float*)d_in[5];
    const float* Wv   = (const float*)d_in[6];
    const float* bv   = (const float*)d_in[7];
    float* out = (float*)d_out;

    init_kernel<<<(NN + 255) / 256, 256>>>(Wq, bq, Wk, bk, Wv, bv);

    qkv_gemm<<<(NN + 63) / 64, 256>>>(x);

    count_kernel<<<(EE + 255) / 256, 256>>>(edge);
    scan1_kernel<<<SCAN_NB, SCAN_B>>>();
    scan3_kernel<<<SCAN_NB, SCAN_B>>>();
    scatter_kernel<<<(EE + 255) / 256, 256>>>(edge);

    agg_kernel<<<(NN + 7) / 8, 256>>>(out);
}